// round 5
// baseline (speedup 1.0000x reference)
#include <cuda_runtime.h>
#include <cstdint>
#include <cstddef>

#define B_   32
#define S_   512
#define E_   512
#define H_   1024
#define V_   5000
#define G4_  4096
#define MR_  16384      // B*S
#define NCTA 128        // persistent LSTM CTAs

// ---------------------------------------------------------------------------
// Static device scratch (allocation-free per harness rules)
// ---------------------------------------------------------------------------
__device__ float    g_xg[(size_t)MR_ * G4_];   // [B,S,4H] input-gate precompute
__device__ float    g_h [(size_t)MR_ * H_];    // [B,S,H] hidden states
__device__ float    g_hzero[B_ * H_];          // zero h_{-1} (zero-initialized)
__device__ unsigned g_arrive;                  // grid-barrier arrival counter

// ---------------------------------------------------------------------------
// tf32 helpers
// ---------------------------------------------------------------------------
__device__ __forceinline__ unsigned f2tf(float x) {
    unsigned r;
    asm("cvt.rna.tf32.f32 %0, %1;" : "=r"(r) : "f"(x));
    return r;
}

__device__ __forceinline__ void mma8(float* c, const unsigned* a, const unsigned* b) {
    asm volatile(
        "mma.sync.aligned.m16n8k8.row.col.f32.tf32.tf32.f32 "
        "{%0,%1,%2,%3},{%4,%5,%6,%7},{%8,%9},{%0,%1,%2,%3};\n"
        : "+f"(c[0]), "+f"(c[1]), "+f"(c[2]), "+f"(c[3])
        : "r"(a[0]), "r"(a[1]), "r"(a[2]), "r"(a[3]), "r"(b[0]), "r"(b[1]));
}

// ---------------------------------------------------------------------------
// Generic tf32 GEMM: C[M,N] = A[M,K] @ Wt[N,K]^T (+bias). Optional gather on A.
// BM=BN=128, BK=16, 256 threads, 8 warps in 2(m) x 4(n), warp tile 64x32.
// ---------------------------------------------------------------------------
#define BM 128
#define BN 128
#define BK 16

template<bool GATHER, int NBIAS>
__global__ __launch_bounds__(256)
void gemm_tf32(const float* __restrict__ A, const int* __restrict__ idx,
               const float* __restrict__ Wt, const float* __restrict__ b0p,
               const float* __restrict__ b1p, float* __restrict__ C,
               int M, int N, int K)
{
    __shared__ __align__(16) unsigned As[2][BM][BK + 4];
    __shared__ __align__(16) unsigned Bs[2][BN][BK + 4];

    const int tid  = threadIdx.x;
    const int lane = tid & 31, warp = tid >> 5;
    const int wm   = warp & 1,  wn  = warp >> 1;
    const int quad = lane >> 2, tq  = lane & 3;
    const int m0   = blockIdx.y * BM, n0 = blockIdx.x * BN;
    const int lrow = tid >> 2;          // 0..63
    const int lk   = (tid & 3) * 4;     // 0,4,8,12

    const float* ap[2];
    const float* bp[2];
    bool bv[2];
#pragma unroll
    for (int i = 0; i < 2; i++) {
        int m = m0 + lrow + 64 * i;
        int gidx = GATHER ? idx[m] : m;
        ap[i] = A + (size_t)gidx * K + lk;
        int n = n0 + lrow + 64 * i;
        bv[i] = (n < N);
        bp[i] = Wt + (size_t)(bv[i] ? n : 0) * K + lk;
    }

    float acc[4][4][4];
#pragma unroll
    for (int mi = 0; mi < 4; mi++)
#pragma unroll
        for (int nj = 0; nj < 4; nj++)
#pragma unroll
            for (int r = 0; r < 4; r++) acc[mi][nj][r] = 0.f;

    // stage 0
#pragma unroll
    for (int i = 0; i < 2; i++) {
        float4 va = *(const float4*)ap[i];
        *(uint4*)&As[0][lrow + 64 * i][lk] =
            make_uint4(f2tf(va.x), f2tf(va.y), f2tf(va.z), f2tf(va.w));
        float4 vb = make_float4(0.f, 0.f, 0.f, 0.f);
        if (bv[i]) vb = *(const float4*)bp[i];
        *(uint4*)&Bs[0][lrow + 64 * i][lk] =
            make_uint4(f2tf(vb.x), f2tf(vb.y), f2tf(vb.z), f2tf(vb.w));
    }
    __syncthreads();

    const int KT = K / BK;
    for (int kt = 0; kt < KT; kt++) {
        const int buf = kt & 1;
        float4 na[2], nb[2];
        if (kt + 1 < KT) {
#pragma unroll
            for (int i = 0; i < 2; i++) {
                na[i] = *(const float4*)(ap[i] + (kt + 1) * BK);
                nb[i] = make_float4(0.f, 0.f, 0.f, 0.f);
                if (bv[i]) nb[i] = *(const float4*)(bp[i] + (kt + 1) * BK);
            }
        }
#pragma unroll
        for (int ks = 0; ks < 2; ks++) {
            const int k0 = ks * 8;
            unsigned a[4][4], b[4][2];
#pragma unroll
            for (int mi = 0; mi < 4; mi++) {
                const int r = wm * 64 + mi * 16;
                a[mi][0] = As[buf][r + quad    ][k0 + tq];
                a[mi][1] = As[buf][r + quad + 8][k0 + tq];
                a[mi][2] = As[buf][r + quad    ][k0 + tq + 4];
                a[mi][3] = As[buf][r + quad + 8][k0 + tq + 4];
            }
#pragma unroll
            for (int nj = 0; nj < 4; nj++) {
                const int cc = wn * 32 + nj * 8;
                b[nj][0] = Bs[buf][cc + quad][k0 + tq];
                b[nj][1] = Bs[buf][cc + quad][k0 + tq + 4];
            }
#pragma unroll
            for (int mi = 0; mi < 4; mi++)
#pragma unroll
                for (int nj = 0; nj < 4; nj++)
                    mma8(acc[mi][nj], a[mi], b[nj]);
        }
        if (kt + 1 < KT) {
#pragma unroll
            for (int i = 0; i < 2; i++) {
                *(uint4*)&As[buf ^ 1][lrow + 64 * i][lk] =
                    make_uint4(f2tf(na[i].x), f2tf(na[i].y), f2tf(na[i].z), f2tf(na[i].w));
                *(uint4*)&Bs[buf ^ 1][lrow + 64 * i][lk] =
                    make_uint4(f2tf(nb[i].x), f2tf(nb[i].y), f2tf(nb[i].z), f2tf(nb[i].w));
            }
            __syncthreads();
        }
    }

    // epilogue (+bias), N may be ragged (5000); N is even so col+1 check folds in
#pragma unroll
    for (int mi = 0; mi < 4; mi++) {
        const int row = m0 + wm * 64 + mi * 16 + quad;
#pragma unroll
        for (int nj = 0; nj < 4; nj++) {
            const int col = n0 + wn * 32 + nj * 8 + tq * 2;
            if (col < N) {
                float bb0 = 0.f, bb1 = 0.f;
                if (NBIAS >= 1) { bb0 = b0p[col];  bb1 = b0p[col + 1]; }
                if (NBIAS >= 2) { bb0 += b1p[col]; bb1 += b1p[col + 1]; }
                float2 v0 = make_float2(acc[mi][nj][0] + bb0, acc[mi][nj][1] + bb1);
                float2 v1 = make_float2(acc[mi][nj][2] + bb0, acc[mi][nj][3] + bb1);
                *(float2*)(C + (size_t)row * N + col)       = v0;
                *(float2*)(C + (size_t)(row + 8) * N + col) = v1;
            }
        }
    }
}

// ---------------------------------------------------------------------------
// Grid-barrier reset (launched before the persistent kernel each replay)
// ---------------------------------------------------------------------------
__global__ void reset_kernel() { g_arrive = 0u; }

// ---------------------------------------------------------------------------
// Persistent LSTM recurrence. 128 CTAs x 256 threads. CTA owns hidden dims
// [cta*8, cta*8+8) -> 32 gate rows (i:0-7, f:8-15, g:16-23, o:24-31).
// W slice resident in SMEM as tf32 (loaded once). Per step:
//   gates[32b x 32r] = h_{t-1}[32 x 1024] @ Wslice^T  (8 warps K-split, tf32 mma)
//   activations per-thread (one (batch, dim) pair each, c in a register)
//   grid barrier (monotone counter)
// Dynamic smem: Ws 32x1028 u32 (131584B) + hs 32x516 u32 (66048B) = 197632B.
// Partial-sum buffer aliases hs after the mma phase.
// ---------------------------------------------------------------------------
__global__ __launch_bounds__(256, 1)
void lstm_kernel(const float* __restrict__ W_hh)
{
    extern __shared__ unsigned sd[];
    unsigned* Ws = sd;                  // [32][1028] tf32
    unsigned* hs = sd + 32 * 1028;      // [32][516]  tf32 (chunk of h)
    float* part  = (float*)hs;          // [8][32][33] partial sums (aliases hs)

    const int tid  = threadIdx.x;
    const int lane = tid & 31, warp = tid >> 5;
    const int quad = lane >> 2, tq = lane & 3;
    const int cta  = blockIdx.x;
    const int j0   = cta * 8;
    const int bb   = tid >> 3, jj = tid & 7;   // activation assignment

    // Load W_hh slice -> tf32 smem (once)
    {
        const int r = tid >> 3, t8 = tid & 7;
        const int gate = r >> 3, jr = r & 7;
        const float* wrow = W_hh + (size_t)(gate * H_ + j0 + jr) * H_;
        unsigned* dst = Ws + r * 1028;
#pragma unroll 4
        for (int i = 0; i < 32; i++) {
            float4 v = *(const float4*)(wrow + t8 * 128 + i * 4);
            dst[t8 * 128 + i * 4 + 0] = f2tf(v.x);
            dst[t8 * 128 + i * 4 + 1] = f2tf(v.y);
            dst[t8 * 128 + i * 4 + 2] = f2tf(v.z);
            dst[t8 * 128 + i * 4 + 3] = f2tf(v.w);
        }
    }

    float c = 0.f;

    for (int t = 0; t < S_; t++) {
        float acc[2][4][4];
#pragma unroll
        for (int mi = 0; mi < 2; mi++)
#pragma unroll
            for (int nj = 0; nj < 4; nj++)
#pragma unroll
                for (int r = 0; r < 4; r++) acc[mi][nj][r] = 0.f;

        for (int kc = 0; kc < 2; kc++) {
            __syncthreads();
            // stage h chunk [32 batches][512 k] fp32 -> tf32
            {
                const int r = tid >> 3, t8 = tid & 7;
                const float* src = (t == 0)
                    ? (g_hzero + (size_t)r * H_ + kc * 512 + t8 * 64)
                    : (g_h + ((size_t)r * S_ + (t - 1)) * H_ + kc * 512 + t8 * 64);
                unsigned* dst = hs + r * 516 + t8 * 64;
#pragma unroll
                for (int i = 0; i < 16; i++) {
                    float4 v = *(const float4*)(src + i * 4);
                    dst[i * 4 + 0] = f2tf(v.x); dst[i * 4 + 1] = f2tf(v.y);
                    dst[i * 4 + 2] = f2tf(v.z); dst[i * 4 + 3] = f2tf(v.w);
                }
            }
            __syncthreads();
            const int kb = warp * 64;            // warp's k slice in this chunk
#pragma unroll
            for (int kt = 0; kt < 8; kt++) {
                const int k0 = kb + kt * 8 + tq;
                unsigned a[2][4], b[4][2];
#pragma unroll
                for (int mi = 0; mi < 2; mi++) {
                    a[mi][0] = hs[(mi * 16 + quad    ) * 516 + k0];
                    a[mi][1] = hs[(mi * 16 + quad + 8) * 516 + k0];
                    a[mi][2] = hs[(mi * 16 + quad    ) * 516 + k0 + 4];
                    a[mi][3] = hs[(mi * 16 + quad + 8) * 516 + k0 + 4];
                }
#pragma unroll
                for (int nj = 0; nj < 4; nj++) {
                    b[nj][0] = Ws[(nj * 8 + quad) * 1028 + kc * 512 + k0];
                    b[nj][1] = Ws[(nj * 8 + quad) * 1028 + kc * 512 + k0 + 4];
                }
#pragma unroll
                for (int mi = 0; mi < 2; mi++)
#pragma unroll
                    for (int nj = 0; nj < 4; nj++)
                        mma8(acc[mi][nj], a[mi], b[nj]);
            }
        }
        __syncthreads();               // all mma reads of hs done -> alias as part

        // write per-warp partials: part[warp][batch 0..31][gate-row 0..31]
#pragma unroll
        for (int mi = 0; mi < 2; mi++)
#pragma unroll
            for (int nj = 0; nj < 4; nj++) {
                float* p0 = part + warp * 1056 + (mi * 16 + quad) * 33 + nj * 8 + tq * 2;
                p0[0] = acc[mi][nj][0]; p0[1] = acc[mi][nj][1];
                float* p1 = p0 + 8 * 33;
                p1[0] = acc[mi][nj][2]; p1[1] = acc[mi][nj][3];
            }
        __syncthreads();

        // activations: one (batch bb, dim jj) pair per thread; c kept in register
        {
            const size_t xrow = ((size_t)bb * S_ + t) * G4_ + j0 + jj;
            float s0 = 0.f, s1 = 0.f, s2 = 0.f, s3 = 0.f;
#pragma unroll
            for (int w = 0; w < 8; w++) {
                const float* p = part + w * 1056 + bb * 33 + jj;
                s0 += p[0]; s1 += p[8]; s2 += p[16]; s3 += p[24];
            }
            s0 += g_xg[xrow];
            s1 += g_xg[xrow + H_];
            s2 += g_xg[xrow + 2 * H_];
            s3 += g_xg[xrow + 3 * H_];
            const float si = 1.f / (1.f + expf(-s0));
            const float sf = 1.f / (1.f + expf(-s1));
            const float gg = tanhf(s2);
            const float so = 1.f / (1.f + expf(-s3));
            c = sf * c + si * gg;
            const float h = so * tanhf(c);
            g_h[((size_t)bb * S_ + t) * H_ + j0 + jj] = h;
        }

        // grid barrier: all h_t visible before any CTA reads it at t+1
        __threadfence();
        __syncthreads();
        if (tid == 0) {
            atomicAdd(&g_arrive, 1u);
            const unsigned target = (unsigned)(t + 1) * NCTA;
            while (*(volatile unsigned*)&g_arrive < target) { }
            __threadfence();
        }
        __syncthreads();
    }
}

// ---------------------------------------------------------------------------
// Launch: phase1 gather-GEMM -> reset -> persistent LSTM -> phase3 GEMM
// ---------------------------------------------------------------------------
extern "C" void kernel_launch(void* const* d_in, const int* in_sizes, int n_in,
                              void* d_out, int out_size)
{
    const int*   x    = (const int*)  d_in[0];
    const float* emb  = (const float*)d_in[1];
    const float* W_ih = (const float*)d_in[2];
    const float* W_hh = (const float*)d_in[3];
    const float* b_ih = (const float*)d_in[4];
    const float* b_hh = (const float*)d_in[5];
    const float* W_fc = (const float*)d_in[6];
    const float* b_fc = (const float*)d_in[7];
    float* out = (float*)d_out;

    float *p_xg, *p_h;
    cudaGetSymbolAddress((void**)&p_xg, g_xg);
    cudaGetSymbolAddress((void**)&p_h,  g_h);
    cudaFuncSetAttribute(lstm_kernel,
                         cudaFuncAttributeMaxDynamicSharedMemorySize, 197632);

    // Phase 1: xg = emb[x] @ W_ih^T + b_ih + b_hh   [16384 x 4096], K=512
    gemm_tf32<true, 2><<<dim3(G4_ / BN, MR_ / BM), 256>>>(
        emb, x, W_ih, b_ih, b_hh, p_xg, MR_, G4_, E_);

    // Phase 2: recurrence (persistent, grid-barriered)
    reset_kernel<<<1, 1>>>();
    lstm_kernel<<<NCTA, 256, 197632>>>(W_hh);

    // Phase 3: logits = h @ W_fc^T + b_fc   [16384 x 5000], K=1024
    gemm_tf32<false, 1><<<dim3((V_ + BN - 1) / BN, MR_ / BM), 256>>>(
        p_h, nullptr, W_fc, b_fc, nullptr, out, MR_, V_, H_);
}

// round 6
// speedup vs baseline: 1.1535x; 1.1535x over previous
#include <cuda_runtime.h>
#include <cstdint>
#include <cstddef>

#define B_   32
#define S_   512
#define E_   512
#define H_   1024
#define V_   5000
#define G4_  4096
#define MR_  16384      // B*S
#define NCTA 128        // persistent LSTM CTAs

// ---------------------------------------------------------------------------
// Static device scratch (allocation-free per harness rules)
// ---------------------------------------------------------------------------
__device__ float    g_xg[(size_t)MR_ * G4_];     // [B,S,4H] input-gate precompute
__device__ unsigned g_htf[(size_t)MR_ * H_];     // [B,S,H] hidden states, tf32 bits
__device__ unsigned g_hzero[B_ * H_];            // zero h_{-1} (tf32 bits of 0.0)
__device__ unsigned g_arrive;                    // grid-barrier arrival counter

// ---------------------------------------------------------------------------
// tf32 / mma / cp.async helpers
// ---------------------------------------------------------------------------
__device__ __forceinline__ unsigned f2tf(float x) {
    unsigned r;
    asm("cvt.rna.tf32.f32 %0, %1;" : "=r"(r) : "f"(x));
    return r;
}

__device__ __forceinline__ void mma8(float* c, const unsigned* a, const unsigned* b) {
    asm volatile(
        "mma.sync.aligned.m16n8k8.row.col.f32.tf32.tf32.f32 "
        "{%0,%1,%2,%3},{%4,%5,%6,%7},{%8,%9},{%0,%1,%2,%3};\n"
        : "+f"(c[0]), "+f"(c[1]), "+f"(c[2]), "+f"(c[3])
        : "r"(a[0]), "r"(a[1]), "r"(a[2]), "r"(a[3]), "r"(b[0]), "r"(b[1]));
}

__device__ __forceinline__ void cpasync16(void* smem, const void* g) {
    unsigned s = (unsigned)__cvta_generic_to_shared(smem);
    asm volatile("cp.async.cg.shared.global [%0], [%1], 16;\n" :: "r"(s), "l"(g));
}
__device__ __forceinline__ void cp_commit() {
    asm volatile("cp.async.commit_group;\n" ::: "memory");
}
__device__ __forceinline__ void cp_wait1() {
    asm volatile("cp.async.wait_group 1;\n" ::: "memory");
}
__device__ __forceinline__ void cp_wait0() {
    asm volatile("cp.async.wait_group 0;\n" ::: "memory");
}

__device__ __forceinline__ float fsigmoid(float x) {
    return __fdividef(1.f, 1.f + __expf(-x));
}
__device__ __forceinline__ float ftanh(float x) {
    return __fdividef(2.f, 1.f + __expf(-2.f * x)) - 1.f;
}

// ---------------------------------------------------------------------------
// Generic tf32 GEMM: C[M,N] = A[M,K] @ Wt[N,K]^T (+bias). Optional gather on A.
// ATF32: A already holds tf32 bit patterns (skip convert).
// BM=BN=128, BK=16, 256 threads, 8 warps in 2(m) x 4(n), warp tile 64x32.
// ---------------------------------------------------------------------------
#define BM 128
#define BN 128
#define BK 16

template<bool GATHER, bool ATF32, int NBIAS>
__global__ __launch_bounds__(256)
void gemm_tf32(const float* __restrict__ A, const int* __restrict__ idx,
               const float* __restrict__ Wt, const float* __restrict__ b0p,
               const float* __restrict__ b1p, float* __restrict__ C,
               int M, int N, int K)
{
    __shared__ __align__(16) unsigned As[2][BM][BK + 4];
    __shared__ __align__(16) unsigned Bs[2][BN][BK + 4];

    const int tid  = threadIdx.x;
    const int lane = tid & 31, warp = tid >> 5;
    const int wm   = warp & 1,  wn  = warp >> 1;
    const int quad = lane >> 2, tq  = lane & 3;
    const int m0   = blockIdx.y * BM, n0 = blockIdx.x * BN;
    const int lrow = tid >> 2;          // 0..63
    const int lk   = (tid & 3) * 4;     // 0,4,8,12

    const float* ap[2];
    const float* bp[2];
    bool bv[2];
#pragma unroll
    for (int i = 0; i < 2; i++) {
        int m = m0 + lrow + 64 * i;
        int gidx = GATHER ? idx[m] : m;
        ap[i] = A + (size_t)gidx * K + lk;
        int n = n0 + lrow + 64 * i;
        bv[i] = (n < N);
        bp[i] = Wt + (size_t)(bv[i] ? n : 0) * K + lk;
    }

    float acc[4][4][4];
#pragma unroll
    for (int mi = 0; mi < 4; mi++)
#pragma unroll
        for (int nj = 0; nj < 4; nj++)
#pragma unroll
            for (int r = 0; r < 4; r++) acc[mi][nj][r] = 0.f;

    // stage 0
#pragma unroll
    for (int i = 0; i < 2; i++) {
        uint4 ra = *(const uint4*)ap[i];
        if (!ATF32)
            ra = make_uint4(f2tf(__uint_as_float(ra.x)), f2tf(__uint_as_float(ra.y)),
                            f2tf(__uint_as_float(ra.z)), f2tf(__uint_as_float(ra.w)));
        *(uint4*)&As[0][lrow + 64 * i][lk] = ra;
        float4 vb = make_float4(0.f, 0.f, 0.f, 0.f);
        if (bv[i]) vb = *(const float4*)bp[i];
        *(uint4*)&Bs[0][lrow + 64 * i][lk] =
            make_uint4(f2tf(vb.x), f2tf(vb.y), f2tf(vb.z), f2tf(vb.w));
    }
    __syncthreads();

    const int KT = K / BK;
    for (int kt = 0; kt < KT; kt++) {
        const int buf = kt & 1;
        uint4  na[2];
        float4 nb[2];
        if (kt + 1 < KT) {
#pragma unroll
            for (int i = 0; i < 2; i++) {
                na[i] = *(const uint4*)(ap[i] + (kt + 1) * BK);
                nb[i] = make_float4(0.f, 0.f, 0.f, 0.f);
                if (bv[i]) nb[i] = *(const float4*)(bp[i] + (kt + 1) * BK);
            }
        }
#pragma unroll
        for (int ks = 0; ks < 2; ks++) {
            const int k0 = ks * 8;
            unsigned a[4][4], b[4][2];
#pragma unroll
            for (int mi = 0; mi < 4; mi++) {
                const int r = wm * 64 + mi * 16;
                a[mi][0] = As[buf][r + quad    ][k0 + tq];
                a[mi][1] = As[buf][r + quad + 8][k0 + tq];
                a[mi][2] = As[buf][r + quad    ][k0 + tq + 4];
                a[mi][3] = As[buf][r + quad + 8][k0 + tq + 4];
            }
#pragma unroll
            for (int nj = 0; nj < 4; nj++) {
                const int cc = wn * 32 + nj * 8;
                b[nj][0] = Bs[buf][cc + quad][k0 + tq];
                b[nj][1] = Bs[buf][cc + quad][k0 + tq + 4];
            }
#pragma unroll
            for (int mi = 0; mi < 4; mi++)
#pragma unroll
                for (int nj = 0; nj < 4; nj++)
                    mma8(acc[mi][nj], a[mi], b[nj]);
        }
        if (kt + 1 < KT) {
#pragma unroll
            for (int i = 0; i < 2; i++) {
                uint4 ra = na[i];
                if (!ATF32)
                    ra = make_uint4(f2tf(__uint_as_float(ra.x)), f2tf(__uint_as_float(ra.y)),
                                    f2tf(__uint_as_float(ra.z)), f2tf(__uint_as_float(ra.w)));
                *(uint4*)&As[buf ^ 1][lrow + 64 * i][lk] = ra;
                *(uint4*)&Bs[buf ^ 1][lrow + 64 * i][lk] =
                    make_uint4(f2tf(nb[i].x), f2tf(nb[i].y), f2tf(nb[i].z), f2tf(nb[i].w));
            }
            __syncthreads();
        }
    }

    // epilogue (+bias); N even, col even -> col+1 < N implied by col < N
#pragma unroll
    for (int mi = 0; mi < 4; mi++) {
        const int row = m0 + wm * 64 + mi * 16 + quad;
#pragma unroll
        for (int nj = 0; nj < 4; nj++) {
            const int col = n0 + wn * 32 + nj * 8 + tq * 2;
            if (col < N) {
                float bb0 = 0.f, bb1 = 0.f;
                if (NBIAS >= 1) { bb0 = b0p[col];  bb1 = b0p[col + 1]; }
                if (NBIAS >= 2) { bb0 += b1p[col]; bb1 += b1p[col + 1]; }
                float2 v0 = make_float2(acc[mi][nj][0] + bb0, acc[mi][nj][1] + bb1);
                float2 v1 = make_float2(acc[mi][nj][2] + bb0, acc[mi][nj][3] + bb1);
                *(float2*)(C + (size_t)row * N + col)       = v0;
                *(float2*)(C + (size_t)(row + 8) * N + col) = v1;
            }
        }
    }
}

// ---------------------------------------------------------------------------
__global__ void reset_kernel() { g_arrive = 0u; }

// ---------------------------------------------------------------------------
// Persistent LSTM recurrence. 128 CTAs x 256 threads. CTA owns hidden dims
// [cta*8, cta*8+8) -> 32 gate rows (i,f,g,o x 8).
// W slice resident in SMEM as tf32. h circulates in GLOBAL as tf32 bits; the
// consumer stages it with cp.async (no convert) in four 256-k chunks with a
// 2-deep pipeline so chunk c+1 loads overlap chunk c MMAs.
// smem: Ws 32x1032 u32 (132096B) + hb 2x32x264 u32 (67584B) = 199680B.
// Partial-sum buffer [8][32][34] f32 aliases hb after the MMA phase.
// ---------------------------------------------------------------------------
#define WS_STR 1032
#define HB_STR 264
#define HB_ELE (32 * HB_STR)            // per buffer, u32
#define SMEM_LSTM (32 * WS_STR * 4 + 2 * HB_ELE * 4)

__global__ __launch_bounds__(256, 1)
void lstm_kernel(const float* __restrict__ W_hh)
{
    extern __shared__ unsigned sd[];
    unsigned* Ws = sd;                       // [32][1032]
    unsigned* hb = sd + 32 * WS_STR;         // [2][32][264]
    float* part  = (float*)hb;               // [8][32][34] (aliases hb)

    const int tid  = threadIdx.x;
    const int lane = tid & 31, warp = tid >> 5;
    const int quad = lane >> 2, tq = lane & 3;
    const int j0   = blockIdx.x * 8;
    const int bb   = tid >> 3, jj = tid & 7;   // activation (batch, dim)
    const int r8   = tid >> 3, t8 = tid & 7;   // staging (row, 1/8 slice)

    // Load W_hh slice -> tf32 smem (once)
    {
        const int gate = r8 >> 3, jr = r8 & 7;
        const float* wrow = W_hh + (size_t)(gate * H_ + j0 + jr) * H_ + t8 * 128;
        unsigned* dst = Ws + r8 * WS_STR + t8 * 128;
#pragma unroll 8
        for (int i = 0; i < 32; i++) {
            float4 v = *(const float4*)(wrow + i * 4);
            dst[i * 4 + 0] = f2tf(v.x); dst[i * 4 + 1] = f2tf(v.y);
            dst[i * 4 + 2] = f2tf(v.z); dst[i * 4 + 3] = f2tf(v.w);
        }
    }

    float c = 0.f;
    const size_t xbase = ((size_t)bb * S_) * G4_ + j0 + jj;
    const unsigned* hz = g_hzero + (size_t)r8 * H_ + t8 * 32;

    for (int t = 0; t < S_; t++) {
        // prefetch xg (DRAM, independent of h) — consumed after the reduce
        const size_t xrow = xbase + (size_t)t * G4_;
        const float x0 = __ldcs(&g_xg[xrow]);
        const float x1 = __ldcs(&g_xg[xrow + H_]);
        const float x2 = __ldcs(&g_xg[xrow + 2 * H_]);
        const float x3 = __ldcs(&g_xg[xrow + 3 * H_]);

        const unsigned* hsrc = (t == 0)
            ? hz
            : g_htf + ((size_t)r8 * S_ + (t - 1)) * H_ + t8 * 32;

        float acc[2][4][4];
#pragma unroll
        for (int mi = 0; mi < 2; mi++)
#pragma unroll
            for (int nj = 0; nj < 4; nj++)
#pragma unroll
                for (int r = 0; r < 4; r++) acc[mi][nj][r] = 0.f;

        // stage chunks 0 and 1
#pragma unroll
        for (int cc = 0; cc < 2; cc++) {
            unsigned* dst = hb + cc * HB_ELE + r8 * HB_STR + t8 * 32;
#pragma unroll
            for (int i = 0; i < 8; i++)
                cpasync16(dst + i * 4, hsrc + cc * 256 + i * 4);
            cp_commit();
        }

#pragma unroll
        for (int ck = 0; ck < 4; ck++) {
            const int buf = ck & 1;
            if (ck < 3) cp_wait1(); else cp_wait0();
            __syncthreads();                       // chunk ck resident
            const unsigned* hbb = hb + buf * HB_ELE;
            const int kb = warp * 32;              // warp K slice in chunk
#pragma unroll
            for (int kt = 0; kt < 4; kt++) {
                const int k0 = kb + kt * 8 + tq;
                unsigned a[2][4], b[4][2];
#pragma unroll
                for (int mi = 0; mi < 2; mi++) {
                    a[mi][0] = hbb[(mi * 16 + quad    ) * HB_STR + k0];
                    a[mi][1] = hbb[(mi * 16 + quad + 8) * HB_STR + k0];
                    a[mi][2] = hbb[(mi * 16 + quad    ) * HB_STR + k0 + 4];
                    a[mi][3] = hbb[(mi * 16 + quad + 8) * HB_STR + k0 + 4];
                }
#pragma unroll
                for (int nj = 0; nj < 4; nj++) {
                    b[nj][0] = Ws[(nj * 8 + quad) * WS_STR + ck * 256 + k0];
                    b[nj][1] = Ws[(nj * 8 + quad) * WS_STR + ck * 256 + k0 + 4];
                }
#pragma unroll
                for (int mi = 0; mi < 2; mi++)
#pragma unroll
                    for (int nj = 0; nj < 4; nj++)
                        mma8(acc[mi][nj], a[mi], b[nj]);
            }
            __syncthreads();                       // all warps done reading buf
            if (ck + 2 < 4) {                      // stage chunk ck+2 into buf
                unsigned* dst = hb + buf * HB_ELE + r8 * HB_STR + t8 * 32;
#pragma unroll
                for (int i = 0; i < 8; i++)
                    cpasync16(dst + i * 4, hsrc + (ck + 2) * 256 + i * 4);
                cp_commit();
            }
        }

        // per-warp partials: part[warp][batch][34]
#pragma unroll
        for (int mi = 0; mi < 2; mi++)
#pragma unroll
            for (int nj = 0; nj < 4; nj++) {
                float* p0 = part + warp * 1088 + (mi * 16 + quad) * 34 + nj * 8 + tq * 2;
                *(float2*)p0            = make_float2(acc[mi][nj][0], acc[mi][nj][1]);
                *(float2*)(p0 + 8 * 34) = make_float2(acc[mi][nj][2], acc[mi][nj][3]);
            }
        __syncthreads();

        // activations: thread owns (batch bb, dim jj); c stays in a register
        {
            float s0 = x0, s1 = x1, s2 = x2, s3 = x3;
#pragma unroll
            for (int w = 0; w < 8; w++) {
                const float* p = part + w * 1088 + bb * 34 + jj;
                s0 += p[0]; s1 += p[8]; s2 += p[16]; s3 += p[24];
            }
            const float si = fsigmoid(s0);
            const float sf = fsigmoid(s1);
            const float gg = ftanh(s2);
            const float so = fsigmoid(s3);
            c = sf * c + si * gg;
            const float h = so * ftanh(c);
            g_htf[((size_t)bb * S_ + t) * H_ + j0 + jj] = f2tf(h);
        }

        // grid barrier (monotone counter): h_t visible before any t+1 read
        __threadfence();
        __syncthreads();
        if (tid == 0) {
            atomicAdd(&g_arrive, 1u);
            const unsigned target = (unsigned)(t + 1) * NCTA;
            while (*(volatile unsigned*)&g_arrive < target) { }
            __threadfence();
        }
        __syncthreads();
    }
}

// ---------------------------------------------------------------------------
extern "C" void kernel_launch(void* const* d_in, const int* in_sizes, int n_in,
                              void* d_out, int out_size)
{
    const int*   x    = (const int*)  d_in[0];
    const float* emb  = (const float*)d_in[1];
    const float* W_ih = (const float*)d_in[2];
    const float* W_hh = (const float*)d_in[3];
    const float* b_ih = (const float*)d_in[4];
    const float* b_hh = (const float*)d_in[5];
    const float* W_fc = (const float*)d_in[6];
    const float* b_fc = (const float*)d_in[7];
    float* out = (float*)d_out;

    float *p_xg; unsigned *p_htf;
    cudaGetSymbolAddress((void**)&p_xg,  g_xg);
    cudaGetSymbolAddress((void**)&p_htf, g_htf);
    cudaFuncSetAttribute(lstm_kernel,
                         cudaFuncAttributeMaxDynamicSharedMemorySize, SMEM_LSTM);

    // Phase 1: xg = emb[x] @ W_ih^T + b_ih + b_hh   [16384 x 4096], K=512
    gemm_tf32<true, false, 2><<<dim3(G4_ / BN, MR_ / BM), 256>>>(
        emb, x, W_ih, b_ih, b_hh, p_xg, MR_, G4_, E_);

    // Phase 2: recurrence (persistent, grid-barriered)
    reset_kernel<<<1, 1>>>();
    lstm_kernel<<<NCTA, 256, SMEM_LSTM>>>(W_hh);

    // Phase 3: logits = h @ W_fc^T + b_fc   [16384 x 5000], K=1024 (A is tf32 bits)
    gemm_tf32<false, true, 1><<<dim3((V_ + BN - 1) / BN, MR_ / BM), 256>>>(
        (const float*)p_htf, nullptr, W_fc, b_fc, nullptr, out, MR_, V_, H_);
}

// round 7
// speedup vs baseline: 1.9587x; 1.6981x over previous
#include <cuda_runtime.h>
#include <cstdint>
#include <cstddef>

#define B_   32
#define S_   512
#define E_   512
#define H_   1024
#define V_   5000
#define G4_  4096
#define MR_  16384      // B*S
#define NCTA 128        // persistent LSTM CTAs

// ---------------------------------------------------------------------------
// Static device scratch (allocation-free per harness rules)
// ---------------------------------------------------------------------------
__device__ float    g_xg[(size_t)MR_ * G4_];     // [B,S,4H] input-gate precompute
__device__ unsigned g_htf[(size_t)MR_ * H_];     // [B,S,H] hidden states, tf32 bits
__device__ unsigned g_hzero[B_ * H_];            // zero h_{-1} (tf32 bits of 0.0)
__device__ unsigned g_arrive;                    // grid-barrier arrival counter

// ---------------------------------------------------------------------------
// tf32 / mma / cp.async helpers
// ---------------------------------------------------------------------------
__device__ __forceinline__ unsigned f2tf(float x) {
    unsigned r;
    asm("cvt.rna.tf32.f32 %0, %1;" : "=r"(r) : "f"(x));
    return r;
}

__device__ __forceinline__ void mma8(float* c, const unsigned* a, const unsigned* b) {
    asm volatile(
        "mma.sync.aligned.m16n8k8.row.col.f32.tf32.tf32.f32 "
        "{%0,%1,%2,%3},{%4,%5,%6,%7},{%8,%9},{%0,%1,%2,%3};\n"
        : "+f"(c[0]), "+f"(c[1]), "+f"(c[2]), "+f"(c[3])
        : "r"(a[0]), "r"(a[1]), "r"(a[2]), "r"(a[3]), "r"(b[0]), "r"(b[1]));
}

__device__ __forceinline__ void cpasync16(void* smem, const void* g) {
    unsigned s = (unsigned)__cvta_generic_to_shared(smem);
    asm volatile("cp.async.cg.shared.global [%0], [%1], 16;\n" :: "r"(s), "l"(g));
}
__device__ __forceinline__ void cp_commit() {
    asm volatile("cp.async.commit_group;\n" ::: "memory");
}
__device__ __forceinline__ void cp_wait1() {
    asm volatile("cp.async.wait_group 1;\n" ::: "memory");
}
__device__ __forceinline__ void cp_wait0() {
    asm volatile("cp.async.wait_group 0;\n" ::: "memory");
}

__device__ __forceinline__ float fsigmoid(float x) {
    return __fdividef(1.f, 1.f + __expf(-x));
}
__device__ __forceinline__ float ftanh(float x) {
    return __fdividef(2.f, 1.f + __expf(-2.f * x)) - 1.f;
}

// ---------------------------------------------------------------------------
// Generic tf32 GEMM: C[M,N] = A[M,K] @ Wt[N,K]^T (+bias). Optional gather on A.
// ATF32: A already holds tf32 bit patterns (skip convert).
// BM=BN=128, BK=16, 256 threads, 8 warps in 2(m) x 4(n), warp tile 64x32.
// ---------------------------------------------------------------------------
#define BM 128
#define BN 128
#define BK 16

template<bool GATHER, bool ATF32, int NBIAS>
__global__ __launch_bounds__(256)
void gemm_tf32(const float* __restrict__ A, const int* __restrict__ idx,
               const float* __restrict__ Wt, const float* __restrict__ b0p,
               const float* __restrict__ b1p, float* __restrict__ C,
               int M, int N, int K)
{
    __shared__ __align__(16) unsigned As[2][BM][BK + 4];
    __shared__ __align__(16) unsigned Bs[2][BN][BK + 4];

    const int tid  = threadIdx.x;
    const int lane = tid & 31, warp = tid >> 5;
    const int wm   = warp & 1,  wn  = warp >> 1;
    const int quad = lane >> 2, tq  = lane & 3;
    const int m0   = blockIdx.y * BM, n0 = blockIdx.x * BN;
    const int lrow = tid >> 2;          // 0..63
    const int lk   = (tid & 3) * 4;     // 0,4,8,12

    const float* ap[2];
    const float* bp[2];
    bool bv[2];
#pragma unroll
    for (int i = 0; i < 2; i++) {
        int m = m0 + lrow + 64 * i;
        int gidx = GATHER ? idx[m] : m;
        ap[i] = A + (size_t)gidx * K + lk;
        int n = n0 + lrow + 64 * i;
        bv[i] = (n < N);
        bp[i] = Wt + (size_t)(bv[i] ? n : 0) * K + lk;
    }

    float acc[4][4][4];
#pragma unroll
    for (int mi = 0; mi < 4; mi++)
#pragma unroll
        for (int nj = 0; nj < 4; nj++)
#pragma unroll
            for (int r = 0; r < 4; r++) acc[mi][nj][r] = 0.f;

    // stage 0
#pragma unroll
    for (int i = 0; i < 2; i++) {
        uint4 ra = *(const uint4*)ap[i];
        if (!ATF32)
            ra = make_uint4(f2tf(__uint_as_float(ra.x)), f2tf(__uint_as_float(ra.y)),
                            f2tf(__uint_as_float(ra.z)), f2tf(__uint_as_float(ra.w)));
        *(uint4*)&As[0][lrow + 64 * i][lk] = ra;
        float4 vb = make_float4(0.f, 0.f, 0.f, 0.f);
        if (bv[i]) vb = *(const float4*)bp[i];
        *(uint4*)&Bs[0][lrow + 64 * i][lk] =
            make_uint4(f2tf(vb.x), f2tf(vb.y), f2tf(vb.z), f2tf(vb.w));
    }
    __syncthreads();

    const int KT = K / BK;
    for (int kt = 0; kt < KT; kt++) {
        const int buf = kt & 1;
        uint4  na[2];
        float4 nb[2];
        if (kt + 1 < KT) {
#pragma unroll
            for (int i = 0; i < 2; i++) {
                na[i] = *(const uint4*)(ap[i] + (kt + 1) * BK);
                nb[i] = make_float4(0.f, 0.f, 0.f, 0.f);
                if (bv[i]) nb[i] = *(const float4*)(bp[i] + (kt + 1) * BK);
            }
        }
#pragma unroll
        for (int ks = 0; ks < 2; ks++) {
            const int k0 = ks * 8;
            unsigned a[4][4], b[4][2];
#pragma unroll
            for (int mi = 0; mi < 4; mi++) {
                const int r = wm * 64 + mi * 16;
                a[mi][0] = As[buf][r + quad    ][k0 + tq];
                a[mi][1] = As[buf][r + quad + 8][k0 + tq];
                a[mi][2] = As[buf][r + quad    ][k0 + tq + 4];
                a[mi][3] = As[buf][r + quad + 8][k0 + tq + 4];
            }
#pragma unroll
            for (int nj = 0; nj < 4; nj++) {
                const int cc = wn * 32 + nj * 8;
                b[nj][0] = Bs[buf][cc + quad][k0 + tq];
                b[nj][1] = Bs[buf][cc + quad][k0 + tq + 4];
            }
#pragma unroll
            for (int mi = 0; mi < 4; mi++)
#pragma unroll
                for (int nj = 0; nj < 4; nj++)
                    mma8(acc[mi][nj], a[mi], b[nj]);
        }
        if (kt + 1 < KT) {
#pragma unroll
            for (int i = 0; i < 2; i++) {
                uint4 ra = na[i];
                if (!ATF32)
                    ra = make_uint4(f2tf(__uint_as_float(ra.x)), f2tf(__uint_as_float(ra.y)),
                                    f2tf(__uint_as_float(ra.z)), f2tf(__uint_as_float(ra.w)));
                *(uint4*)&As[buf ^ 1][lrow + 64 * i][lk] = ra;
                *(uint4*)&Bs[buf ^ 1][lrow + 64 * i][lk] =
                    make_uint4(f2tf(nb[i].x), f2tf(nb[i].y), f2tf(nb[i].z), f2tf(nb[i].w));
            }
            __syncthreads();
        }
    }

    // epilogue (+bias); N even, col even -> col+1 < N implied by col < N
#pragma unroll
    for (int mi = 0; mi < 4; mi++) {
        const int row = m0 + wm * 64 + mi * 16 + quad;
#pragma unroll
        for (int nj = 0; nj < 4; nj++) {
            const int col = n0 + wn * 32 + nj * 8 + tq * 2;
            if (col < N) {
                float bb0 = 0.f, bb1 = 0.f;
                if (NBIAS >= 1) { bb0 = b0p[col];  bb1 = b0p[col + 1]; }
                if (NBIAS >= 2) { bb0 += b1p[col]; bb1 += b1p[col + 1]; }
                float2 v0 = make_float2(acc[mi][nj][0] + bb0, acc[mi][nj][1] + bb1);
                float2 v1 = make_float2(acc[mi][nj][2] + bb0, acc[mi][nj][3] + bb1);
                *(float2*)(C + (size_t)row * N + col)       = v0;
                *(float2*)(C + (size_t)(row + 8) * N + col) = v1;
            }
        }
    }
}

// ---------------------------------------------------------------------------
__global__ void reset_kernel() { g_arrive = 0u; }

// ---------------------------------------------------------------------------
// Persistent LSTM recurrence. 128 CTAs x 256 threads. CTA owns hidden dims
// [cta*8, cta*8+8) -> 32 gate rows (i,f,g,o x 8).
// Warp w owns K-slice [w*128, w*128+128): stages ONLY its slice via cp.async
// in four 32-k sub-chunks (2 rotating warp-private buffers), synchronized with
// per-warp wait_group + __syncwarp — no __syncthreads in the load/MMA phase.
// smem: Ws [32][1028] tf32 (131584B) + hbuf [8][2][32][36] (73728B) = 205312B.
// Partial buffer [8][32][40] f32 aliases hbuf after the MMA phase.
// ---------------------------------------------------------------------------
#define WS_STR   1028
#define HB_STRD  36
#define HB_BUF   (32 * HB_STRD)         // 1152 u32 per buffer
#define HB_WARP  (2 * HB_BUF)           // 2304 u32 per warp
#define PART_STR 40
#define SMEM_LSTM (32 * WS_STR * 4 + 8 * HB_WARP * 4)   // 205312

__global__ __launch_bounds__(256, 1)
void lstm_kernel(const float* __restrict__ W_hh)
{
    extern __shared__ unsigned sd[];
    unsigned* Ws = sd;                       // [32][1028]
    unsigned* hb = sd + 32 * WS_STR;         // [8][2][32][36]
    float* part  = (float*)hb;               // [8][32][40] (aliases hb)

    const int tid  = threadIdx.x;
    const int lane = tid & 31, warp = tid >> 5;
    const int quad = lane >> 2, tq = lane & 3;
    const int j0   = blockIdx.x * 8;
    const int bb   = tid >> 3, jj = tid & 7;   // activation (batch, dim)
    const int srow = lane >> 3, su = lane & 7; // staging lane roles
    const int kb   = warp * 128;               // warp K-slice base

    // Load W_hh slice -> tf32 smem (once)
    {
        const int r8 = tid >> 3, t8 = tid & 7;
        const int gate = r8 >> 3, jr = r8 & 7;
        const float* wrow = W_hh + (size_t)(gate * H_ + j0 + jr) * H_ + t8 * 128;
        unsigned* dst = Ws + r8 * WS_STR + t8 * 128;
#pragma unroll 8
        for (int i = 0; i < 32; i++) {
            float4 v = *(const float4*)(wrow + i * 4);
            dst[i * 4 + 0] = f2tf(v.x); dst[i * 4 + 1] = f2tf(v.y);
            dst[i * 4 + 2] = f2tf(v.z); dst[i * 4 + 3] = f2tf(v.w);
        }
    }
    __syncthreads();

    unsigned* hw = hb + warp * HB_WARP;
    float c = 0.f;
    const size_t xbase = ((size_t)bb * S_) * G4_ + j0 + jj;

    for (int t = 0; t < S_; t++) {
        // prefetch xg (DRAM, independent of h) — consumed after the reduce
        const size_t xrow = xbase + (size_t)t * G4_;
        const float x0 = __ldcs(&g_xg[xrow]);
        const float x1 = __ldcs(&g_xg[xrow + H_]);
        const float x2 = __ldcs(&g_xg[xrow + 2 * H_]);
        const float x3 = __ldcs(&g_xg[xrow + 3 * H_]);

        // per-lane staging source: row = i*4 + srow, col = kb + s*32 + su*4
        const size_t rstep = (t == 0) ? (size_t)4 * H_ : (size_t)4 * S_ * H_;
        const unsigned* hbase = (t == 0)
            ? g_hzero + (size_t)srow * H_ + kb + su * 4
            : g_htf + (size_t)(t - 1) * H_ + (size_t)srow * S_ * H_ + kb + su * 4;

        float acc[2][4][4];
#pragma unroll
        for (int mi = 0; mi < 2; mi++)
#pragma unroll
            for (int nj = 0; nj < 4; nj++)
#pragma unroll
                for (int r = 0; r < 4; r++) acc[mi][nj][r] = 0.f;

        // stage sub-chunks 0,1 (warp-private)
#pragma unroll
        for (int s = 0; s < 2; s++) {
            unsigned* dst = hw + (s & 1) * HB_BUF + srow * HB_STRD + su * 4;
            const unsigned* src = hbase + s * 32;
#pragma unroll
            for (int i = 0; i < 8; i++)
                cpasync16(dst + i * 4 * HB_STRD, src + i * rstep);
            cp_commit();
        }

#pragma unroll
        for (int s = 0; s < 4; s++) {
            if (s < 3) cp_wait1(); else cp_wait0();
            __syncwarp();                               // sub-chunk s resident (warp-wide)
            const unsigned* hbb = hw + (s & 1) * HB_BUF;
#pragma unroll
            for (int kt = 0; kt < 4; kt++) {
                const int k0 = kt * 8 + tq;
                unsigned a[2][4], b[4][2];
#pragma unroll
                for (int mi = 0; mi < 2; mi++) {
                    a[mi][0] = hbb[(mi * 16 + quad    ) * HB_STRD + k0];
                    a[mi][1] = hbb[(mi * 16 + quad + 8) * HB_STRD + k0];
                    a[mi][2] = hbb[(mi * 16 + quad    ) * HB_STRD + k0 + 4];
                    a[mi][3] = hbb[(mi * 16 + quad + 8) * HB_STRD + k0 + 4];
                }
#pragma unroll
                for (int nj = 0; nj < 4; nj++) {
                    const int wk = kb + s * 32 + kt * 8 + tq;
                    b[nj][0] = Ws[(nj * 8 + quad) * WS_STR + wk];
                    b[nj][1] = Ws[(nj * 8 + quad) * WS_STR + wk + 4];
                }
#pragma unroll
                for (int mi = 0; mi < 2; mi++)
#pragma unroll
                    for (int nj = 0; nj < 4; nj++)
                        mma8(acc[mi][nj], a[mi], b[nj]);
            }
            if (s + 2 < 4) {
                __syncwarp();                           // warp done reading this buf
                unsigned* dst = hw + (s & 1) * HB_BUF + srow * HB_STRD + su * 4;
                const unsigned* src = hbase + (s + 2) * 32;
#pragma unroll
                for (int i = 0; i < 8; i++)
                    cpasync16(dst + i * 4 * HB_STRD, src + i * rstep);
                cp_commit();
            }
        }
        __syncthreads();               // all warps done with hbuf -> alias as part

        // per-warp partials: part[warp][batch][40]
#pragma unroll
        for (int mi = 0; mi < 2; mi++)
#pragma unroll
            for (int nj = 0; nj < 4; nj++) {
                float* p0 = part + warp * (32 * PART_STR)
                          + (mi * 16 + quad) * PART_STR + nj * 8 + tq * 2;
                *(float2*)p0                  = make_float2(acc[mi][nj][0], acc[mi][nj][1]);
                *(float2*)(p0 + 8 * PART_STR) = make_float2(acc[mi][nj][2], acc[mi][nj][3]);
            }
        __syncthreads();

        // activations: thread owns (batch bb, dim jj); c stays in a register
        {
            float s0 = x0, s1 = x1, s2 = x2, s3 = x3;
#pragma unroll
            for (int w = 0; w < 8; w++) {
                const float* p = part + w * (32 * PART_STR) + bb * PART_STR + jj;
                s0 += p[0]; s1 += p[8]; s2 += p[16]; s3 += p[24];
            }
            const float si = fsigmoid(s0);
            const float sf = fsigmoid(s1);
            const float gg = ftanh(s2);
            const float so = fsigmoid(s3);
            c = sf * c + si * gg;
            const float h = so * ftanh(c);
            g_htf[((size_t)bb * S_ + t) * H_ + j0 + jj] = f2tf(h);
        }

        // grid barrier (tid0-only fences; cumulativity via bar.sync)
        __syncthreads();
        if (tid == 0) {
            __threadfence();
            atomicAdd(&g_arrive, 1u);
            const unsigned target = (unsigned)(t + 1) * NCTA;
            while (*(volatile unsigned*)&g_arrive < target) { }
            __threadfence();
        }
        __syncthreads();
    }
}

// ---------------------------------------------------------------------------
extern "C" void kernel_launch(void* const* d_in, const int* in_sizes, int n_in,
                              void* d_out, int out_size)
{
    const int*   x    = (const int*)  d_in[0];
    const float* emb  = (const float*)d_in[1];
    const float* W_ih = (const float*)d_in[2];
    const float* W_hh = (const float*)d_in[3];
    const float* b_ih = (const float*)d_in[4];
    const float* b_hh = (const float*)d_in[5];
    const float* W_fc = (const float*)d_in[6];
    const float* b_fc = (const float*)d_in[7];
    float* out = (float*)d_out;

    float *p_xg; unsigned *p_htf;
    cudaGetSymbolAddress((void**)&p_xg,  g_xg);
    cudaGetSymbolAddress((void**)&p_htf, g_htf);
    cudaFuncSetAttribute(lstm_kernel,
                         cudaFuncAttributeMaxDynamicSharedMemorySize, SMEM_LSTM);

    // Phase 1: xg = emb[x] @ W_ih^T + b_ih + b_hh   [16384 x 4096], K=512
    gemm_tf32<true, false, 2><<<dim3(G4_ / BN, MR_ / BM), 256>>>(
        emb, x, W_ih, b_ih, b_hh, p_xg, MR_, G4_, E_);

    // Phase 2: recurrence (persistent, grid-barriered)
    reset_kernel<<<1, 1>>>();
    lstm_kernel<<<NCTA, 256, SMEM_LSTM>>>(W_hh);

    // Phase 3: logits = h @ W_fc^T + b_fc   [16384 x 5000], K=1024 (A is tf32 bits)
    gemm_tf32<false, true, 1><<<dim3((V_ + BN - 1) / BN, MR_ / BM), 256>>>(
        (const float*)p_htf, nullptr, W_fc, b_fc, nullptr, out, MR_, V_, H_);
}

// round 9
// speedup vs baseline: 2.0792x; 1.0615x over previous
#include <cuda_runtime.h>
#include <cstdint>
#include <cstddef>

#define B_   32
#define S_   512
#define E_   512
#define H_   1024
#define V_   5000
#define G4_  4096
#define MR_  16384      // B*S
#define NCTA 128        // persistent LSTM CTAs

// ---------------------------------------------------------------------------
// Static device scratch (allocation-free per harness rules)
// ---------------------------------------------------------------------------
__device__ float    g_xg[(size_t)MR_ * G4_];     // [B,S,4H] input-gate precompute
__device__ unsigned g_htf[(size_t)MR_ * H_];     // [B,S,H] hidden states, tf32 bits
__device__ unsigned g_hzero[B_ * H_];            // zero h_{-1} (tf32 bits of 0.0)
__device__ unsigned g_arrive;                    // grid-barrier arrival counter

// ---------------------------------------------------------------------------
// tf32 / mma / ldmatrix / cp.async helpers
// ---------------------------------------------------------------------------
__device__ __forceinline__ unsigned f2tf(float x) {
    unsigned r;
    asm("cvt.rna.tf32.f32 %0, %1;" : "=r"(r) : "f"(x));
    return r;
}

__device__ __forceinline__ void mma8(float* c, const unsigned* a, const unsigned* b) {
    asm volatile(
        "mma.sync.aligned.m16n8k8.row.col.f32.tf32.tf32.f32 "
        "{%0,%1,%2,%3},{%4,%5,%6,%7},{%8,%9},{%0,%1,%2,%3};\n"
        : "+f"(c[0]), "+f"(c[1]), "+f"(c[2]), "+f"(c[3])
        : "r"(a[0]), "r"(a[1]), "r"(a[2]), "r"(a[3]), "r"(b[0]), "r"(b[1]));
}

// x4 b16 ldmatrix: 4 m8n8 b16 matrices == 2 8x8 f32 tiles -> tf32 fragments.
__device__ __forceinline__ void ldsm4(unsigned* r, const void* smem_ptr) {
    unsigned a = (unsigned)__cvta_generic_to_shared(smem_ptr);
    asm volatile("ldmatrix.sync.aligned.m8n8.x4.shared.b16 {%0,%1,%2,%3}, [%4];\n"
                 : "=r"(r[0]), "=r"(r[1]), "=r"(r[2]), "=r"(r[3]) : "r"(a));
}

__device__ __forceinline__ void cpasync16(void* smem, const void* g) {
    unsigned s = (unsigned)__cvta_generic_to_shared(smem);
    asm volatile("cp.async.cg.shared.global [%0], [%1], 16;\n" :: "r"(s), "l"(g));
}
__device__ __forceinline__ void cp_commit() {
    asm volatile("cp.async.commit_group;\n" ::: "memory");
}
__device__ __forceinline__ void cp_wait1() {
    asm volatile("cp.async.wait_group 1;\n" ::: "memory");
}
__device__ __forceinline__ void cp_wait0() {
    asm volatile("cp.async.wait_group 0;\n" ::: "memory");
}

__device__ __forceinline__ float fsigmoid(float x) {
    return __fdividef(1.f, 1.f + __expf(-x));
}
__device__ __forceinline__ float ftanh(float x) {
    return __fdividef(2.f, 1.f + __expf(-2.f * x)) - 1.f;
}

// ---------------------------------------------------------------------------
// Generic tf32 GEMM: C[M,N] = A[M,K] @ Wt[N,K]^T (+bias). Optional gather on A.
// ATF32: A already holds tf32 bit patterns (skip convert).
// BM=BN=128, BK=16, 256 threads, 8 warps in 2(m) x 4(n), warp tile 64x32.
// Fragment loads via ldmatrix.x4.b16 (4 LDSM per warp per 8-k vs 24 LDS.32).
// ---------------------------------------------------------------------------
#define BM 128
#define BN 128
#define BK 16

template<bool GATHER, bool ATF32, int NBIAS>
__global__ __launch_bounds__(256)
void gemm_tf32(const float* __restrict__ A, const int* __restrict__ idx,
               const float* __restrict__ Wt, const float* __restrict__ b0p,
               const float* __restrict__ b1p, float* __restrict__ C,
               int M, int N, int K)
{
    __shared__ __align__(16) unsigned As[2][BM][BK + 4];   // row stride 80B (16B mult)
    __shared__ __align__(16) unsigned Bs[2][BN][BK + 4];

    const int tid  = threadIdx.x;
    const int lane = tid & 31, warp = tid >> 5;
    const int wm   = warp & 1,  wn  = warp >> 1;
    const int quad = lane >> 2, tq  = lane & 3;
    const int m0   = blockIdx.y * BM, n0 = blockIdx.x * BN;
    const int lrow = tid >> 2;          // 0..63
    const int lk   = (tid & 3) * 4;     // 0,4,8,12

    // ldmatrix per-lane address roles
    const int arow  = wm * 64 + (lane & 15);          // A: rows, +mi*16
    const int acol4 = (lane >> 4) * 4;                //    k sub-offset
    const int brow  = wn * 32 + (lane & 7) + ((lane >> 4) & 1) * 8;  // B: + p*16
    const int bcol4 = ((lane >> 3) & 1) * 4;

    const float* ap[2];
    const float* bp[2];
    bool bv[2];
#pragma unroll
    for (int i = 0; i < 2; i++) {
        int m = m0 + lrow + 64 * i;
        int gidx = GATHER ? idx[m] : m;
        ap[i] = A + (size_t)gidx * K + lk;
        int n = n0 + lrow + 64 * i;
        bv[i] = (n < N);
        bp[i] = Wt + (size_t)(bv[i] ? n : 0) * K + lk;
    }

    float acc[4][4][4];
#pragma unroll
    for (int mi = 0; mi < 4; mi++)
#pragma unroll
        for (int nj = 0; nj < 4; nj++)
#pragma unroll
            for (int r = 0; r < 4; r++) acc[mi][nj][r] = 0.f;

    // stage 0
#pragma unroll
    for (int i = 0; i < 2; i++) {
        uint4 ra = *(const uint4*)ap[i];
        if (!ATF32)
            ra = make_uint4(f2tf(__uint_as_float(ra.x)), f2tf(__uint_as_float(ra.y)),
                            f2tf(__uint_as_float(ra.z)), f2tf(__uint_as_float(ra.w)));
        *(uint4*)&As[0][lrow + 64 * i][lk] = ra;
        float4 vb = make_float4(0.f, 0.f, 0.f, 0.f);
        if (bv[i]) vb = *(const float4*)bp[i];
        *(uint4*)&Bs[0][lrow + 64 * i][lk] =
            make_uint4(f2tf(vb.x), f2tf(vb.y), f2tf(vb.z), f2tf(vb.w));
    }
    __syncthreads();

    const int KT = K / BK;
    for (int kt = 0; kt < KT; kt++) {
        const int buf = kt & 1;
        uint4  na[2];
        float4 nb[2];
        if (kt + 1 < KT) {
#pragma unroll
            for (int i = 0; i < 2; i++) {
                na[i] = *(const uint4*)(ap[i] + (kt + 1) * BK);
                nb[i] = make_float4(0.f, 0.f, 0.f, 0.f);
                if (bv[i]) nb[i] = *(const float4*)(bp[i] + (kt + 1) * BK);
            }
        }
#pragma unroll
        for (int ks = 0; ks < 2; ks++) {
            const int k0 = ks * 8;
            unsigned a[4][4], bb[2][4];
#pragma unroll
            for (int mi = 0; mi < 4; mi++)
                ldsm4(a[mi], &As[buf][arow + mi * 16][k0 + acol4]);
#pragma unroll
            for (int p = 0; p < 2; p++)
                ldsm4(bb[p], &Bs[buf][brow + p * 16][k0 + bcol4]);
#pragma unroll
            for (int mi = 0; mi < 4; mi++)
#pragma unroll
                for (int nj = 0; nj < 4; nj++)
                    mma8(acc[mi][nj], a[mi], &bb[nj >> 1][(nj & 1) * 2]);
        }
        if (kt + 1 < KT) {
#pragma unroll
            for (int i = 0; i < 2; i++) {
                uint4 ra = na[i];
                if (!ATF32)
                    ra = make_uint4(f2tf(__uint_as_float(ra.x)), f2tf(__uint_as_float(ra.y)),
                                    f2tf(__uint_as_float(ra.z)), f2tf(__uint_as_float(ra.w)));
                *(uint4*)&As[buf ^ 1][lrow + 64 * i][lk] = ra;
                *(uint4*)&Bs[buf ^ 1][lrow + 64 * i][lk] =
                    make_uint4(f2tf(nb[i].x), f2tf(nb[i].y), f2tf(nb[i].z), f2tf(nb[i].w));
            }
            __syncthreads();
        }
    }

    // epilogue (+bias); N even, col even -> col+1 < N implied by col < N
#pragma unroll
    for (int mi = 0; mi < 4; mi++) {
        const int row = m0 + wm * 64 + mi * 16 + quad;
#pragma unroll
        for (int nj = 0; nj < 4; nj++) {
            const int col = n0 + wn * 32 + nj * 8 + tq * 2;
            if (col < N) {
                float bb0 = 0.f, bb1 = 0.f;
                if (NBIAS >= 1) { bb0 = b0p[col];  bb1 = b0p[col + 1]; }
                if (NBIAS >= 2) { bb0 += b1p[col]; bb1 += b1p[col + 1]; }
                float2 v0 = make_float2(acc[mi][nj][0] + bb0, acc[mi][nj][1] + bb1);
                float2 v1 = make_float2(acc[mi][nj][2] + bb0, acc[mi][nj][3] + bb1);
                *(float2*)(C + (size_t)row * N + col)       = v0;
                *(float2*)(C + (size_t)(row + 8) * N + col) = v1;
            }
        }
    }
}

// ---------------------------------------------------------------------------
__global__ void reset_kernel() { g_arrive = 0u; }

// ---------------------------------------------------------------------------
// Persistent LSTM recurrence. 128 CTAs x 256 threads. CTA owns hidden dims
// [cta*8, cta*8+8) -> 32 gate rows (i,f,g,o x 8).
// Warp w owns K-slice [w*128, w*128+128): stages ONLY its slice via cp.async
// in four 32-k sub-chunks (2 rotating warp-private buffers), per-warp
// wait_group + __syncwarp; fragments via ldmatrix.x4.b16.
// smem: Ws [32][1028] tf32 (131584B) + hbuf [8][2][32][36] (73728B) = 205312B.
// Partial buffer [8][32][40] f32 aliases hbuf after the MMA phase.
// ---------------------------------------------------------------------------
#define WS_STR   1028
#define HB_STRD  36
#define HB_BUF   (32 * HB_STRD)         // 1152 u32 per buffer
#define HB_WARP  (2 * HB_BUF)           // 2304 u32 per warp
#define PART_STR 40
#define SMEM_LSTM (32 * WS_STR * 4 + 8 * HB_WARP * 4)   // 205312

__global__ __launch_bounds__(256, 1)
void lstm_kernel(const float* __restrict__ W_hh)
{
    extern __shared__ unsigned sd[];
    unsigned* Ws = sd;                       // [32][1028]
    unsigned* hb = sd + 32 * WS_STR;         // [8][2][32][36]
    float* part  = (float*)hb;               // [8][32][40] (aliases hb)

    const int tid  = threadIdx.x;
    const int lane = tid & 31, warp = tid >> 5;
    const int j0   = blockIdx.x * 8;
    const int bb   = tid >> 3, jj = tid & 7;   // activation (batch, dim)
    const int srow = lane >> 3, su = lane & 7; // staging lane roles
    const int kb   = warp * 128;               // warp K-slice base

    // ldmatrix per-lane address roles
    const int arow  = lane & 15;                                   // + mi*16
    const int acol4 = (lane >> 4) * 4;
    const int brow  = (lane & 7) + ((lane >> 4) & 1) * 8;          // + p*16
    const int bcol4 = ((lane >> 3) & 1) * 4;

    // Load W_hh slice -> tf32 smem (once)
    {
        const int r8 = tid >> 3, t8 = tid & 7;
        const int gate = r8 >> 3, jr = r8 & 7;
        const float* wrow = W_hh + (size_t)(gate * H_ + j0 + jr) * H_ + t8 * 128;
        unsigned* dst = Ws + r8 * WS_STR + t8 * 128;
#pragma unroll 8
        for (int i = 0; i < 32; i++) {
            float4 v = *(const float4*)(wrow + i * 4);
            dst[i * 4 + 0] = f2tf(v.x); dst[i * 4 + 1] = f2tf(v.y);
            dst[i * 4 + 2] = f2tf(v.z); dst[i * 4 + 3] = f2tf(v.w);
        }
    }
    __syncthreads();

    unsigned* hw = hb + warp * HB_WARP;
    float c = 0.f;
    const size_t xbase = ((size_t)bb * S_) * G4_ + j0 + jj;

    for (int t = 0; t < S_; t++) {
        // prefetch xg (DRAM, independent of h) — consumed after the reduce
        const size_t xrow = xbase + (size_t)t * G4_;
        const float x0 = __ldcs(&g_xg[xrow]);
        const float x1 = __ldcs(&g_xg[xrow + H_]);
        const float x2 = __ldcs(&g_xg[xrow + 2 * H_]);
        const float x3 = __ldcs(&g_xg[xrow + 3 * H_]);

        // per-lane staging source: row = i*4 + srow, col = kb + s*32 + su*4
        const size_t rstep = (t == 0) ? (size_t)4 * H_ : (size_t)4 * S_ * H_;
        const unsigned* hbase = (t == 0)
            ? g_hzero + (size_t)srow * H_ + kb + su * 4
            : g_htf + (size_t)(t - 1) * H_ + (size_t)srow * S_ * H_ + kb + su * 4;

        float acc[2][4][4];
#pragma unroll
        for (int mi = 0; mi < 2; mi++)
#pragma unroll
            for (int nj = 0; nj < 4; nj++)
#pragma unroll
                for (int r = 0; r < 4; r++) acc[mi][nj][r] = 0.f;

        // stage sub-chunks 0,1 (warp-private)
#pragma unroll
        for (int s = 0; s < 2; s++) {
            unsigned* dst = hw + (s & 1) * HB_BUF + srow * HB_STRD + su * 4;
            const unsigned* src = hbase + s * 32;
#pragma unroll
            for (int i = 0; i < 8; i++)
                cpasync16(dst + i * 4 * HB_STRD, src + i * rstep);
            cp_commit();
        }

#pragma unroll
        for (int s = 0; s < 4; s++) {
            if (s < 3) cp_wait1(); else cp_wait0();
            __syncwarp();                               // sub-chunk s resident (warp-wide)
            const unsigned* hbb = hw + (s & 1) * HB_BUF;
#pragma unroll
            for (int kt = 0; kt < 4; kt++) {
                const int k0 = kt * 8;
                const int wk0 = kb + s * 32 + k0;
                unsigned a[2][4], bw[2][4];
#pragma unroll
                for (int mi = 0; mi < 2; mi++)
                    ldsm4(a[mi], &hbb[(mi * 16 + arow) * HB_STRD + k0 + acol4]);
#pragma unroll
                for (int p = 0; p < 2; p++)
                    ldsm4(bw[p], &Ws[(p * 16 + brow) * WS_STR + wk0 + bcol4]);
#pragma unroll
                for (int mi = 0; mi < 2; mi++)
#pragma unroll
                    for (int nj = 0; nj < 4; nj++)
                        mma8(acc[mi][nj], a[mi], &bw[nj >> 1][(nj & 1) * 2]);
            }
            if (s + 2 < 4) {
                __syncwarp();                           // warp done reading this buf
                unsigned* dst = hw + (s & 1) * HB_BUF + srow * HB_STRD + su * 4;
                const unsigned* src = hbase + (s + 2) * 32;
#pragma unroll
                for (int i = 0; i < 8; i++)
                    cpasync16(dst + i * 4 * HB_STRD, src + i * rstep);
                cp_commit();
            }
        }
        __syncthreads();               // all warps done with hbuf -> alias as part

        // per-warp partials: part[warp][batch][40]
        {
            const int quad = lane >> 2, tq = lane & 3;
#pragma unroll
            for (int mi = 0; mi < 2; mi++)
#pragma unroll
                for (int nj = 0; nj < 4; nj++) {
                    float* p0 = part + warp * (32 * PART_STR)
                              + (mi * 16 + quad) * PART_STR + nj * 8 + tq * 2;
                    *(float2*)p0                  = make_float2(acc[mi][nj][0], acc[mi][nj][1]);
                    *(float2*)(p0 + 8 * PART_STR) = make_float2(acc[mi][nj][2], acc[mi][nj][3]);
                }
        }
        __syncthreads();

        // activations: thread owns (batch bb, dim jj); c stays in a register
        {
            float s0 = x0, s1 = x1, s2 = x2, s3 = x3;
#pragma unroll
            for (int w = 0; w < 8; w++) {
                const float* p = part + w * (32 * PART_STR) + bb * PART_STR + jj;
                s0 += p[0]; s1 += p[8]; s2 += p[16]; s3 += p[24];
            }
            const float si = fsigmoid(s0);
            const float sf = fsigmoid(s1);
            const float gg = ftanh(s2);
            const float so = fsigmoid(s3);
            c = sf * c + si * gg;
            const float h = so * ftanh(c);
            g_htf[((size_t)bb * S_ + t) * H_ + j0 + jj] = f2tf(h);
        }

        // grid barrier (tid0-only fences; cumulativity via bar.sync)
        __syncthreads();
        if (tid == 0) {
            __threadfence();
            atomicAdd(&g_arrive, 1u);
            const unsigned target = (unsigned)(t + 1) * NCTA;
            while (*(volatile unsigned*)&g_arrive < target) { }
            __threadfence();
        }
        __syncthreads();
    }
}

// ---------------------------------------------------------------------------
extern "C" void kernel_launch(void* const* d_in, const int* in_sizes, int n_in,
                              void* d_out, int out_size)
{
    const int*   x    = (const int*)  d_in[0];
    const float* emb  = (const float*)d_in[1];
    const float* W_ih = (const float*)d_in[2];
    const float* W_hh = (const float*)d_in[3];
    const float* b_ih = (const float*)d_in[4];
    const float* b_hh = (const float*)d_in[5];
    const float* W_fc = (const float*)d_in[6];
    const float* b_fc = (const float*)d_in[7];
    float* out = (float*)d_out;

    float *p_xg; unsigned *p_htf;
    cudaGetSymbolAddress((void**)&p_xg,  g_xg);
    cudaGetSymbolAddress((void**)&p_htf, g_htf);
    cudaFuncSetAttribute(lstm_kernel,
                         cudaFuncAttributeMaxDynamicSharedMemorySize, SMEM_LSTM);

    // Phase 1: xg = emb[x] @ W_ih^T + b_ih + b_hh   [16384 x 4096], K=512
    gemm_tf32<true, false, 2><<<dim3(G4_ / BN, MR_ / BM), 256>>>(
        emb, x, W_ih, b_ih, b_hh, p_xg, MR_, G4_, E_);

    // Phase 2: recurrence (persistent, grid-barriered)
    reset_kernel<<<1, 1>>>();
    lstm_kernel<<<NCTA, 256, SMEM_LSTM>>>(W_hh);

    // Phase 3: logits = h @ W_fc^T + b_fc   [16384 x 5000], K=1024 (A is tf32 bits)
    gemm_tf32<false, true, 1><<<dim3((V_ + BN - 1) / BN, MR_ / BM), 256>>>(
        (const float*)p_htf, nullptr, W_fc, b_fc, nullptr, out, MR_, V_, H_);
}